// round 14
// baseline (speedup 1.0000x reference)
#include <cuda_runtime.h>
#include <cuda_bf16.h>
#include <cstdint>
#include <math.h>

// Problem constants
#define NROWS 2048
#define VDIM  50257
#define VPAD  50272   // bf16 row stride
#define H_S   2048
#define H_T   4096
#define NVT   393     // number of 128-wide v tiles

// Scratch (static device allocations)
__device__ __nv_bfloat16 g_logits_s[(size_t)NROWS * VPAD];  // 206 MB
__device__ __nv_bfloat16 g_logits_t[(size_t)NROWS * VPAD];  // 206 MB
__device__ __nv_bfloat16 g_Ws_bf[(size_t)VDIM * H_S];       // 206 MB
__device__ __nv_bfloat16 g_Wt_bf[(size_t)VDIM * H_T];       // 412 MB
__device__ __nv_bfloat16 g_as_bf[(size_t)NROWS * H_S];
__device__ __nv_bfloat16 g_at_bf[(size_t)NROWS * H_T];
__device__ float g_pse_s[(size_t)NROWS * NVT];  // per-tile sumexp partials
__device__ float g_pse_t[(size_t)NROWS * NVT];
__device__ float g_lse[2 * NROWS];
__device__ float g_row_ce[NROWS];
__device__ float g_row_valid[NROWS];
__device__ float g_row_kls[NROWS];
__device__ float g_row_klt[NROWS];

// ---------------------------------------------------------------------------
// Helpers
// ---------------------------------------------------------------------------
__device__ __forceinline__ uint32_t swz(uint32_t row, uint32_t chunk) {
    return row * 128u + ((chunk ^ (row & 7u)) << 4);
}
__device__ __forceinline__ void cp16(uint32_t saddr, const void* gaddr) {
    asm volatile("cp.async.cg.shared.global [%0], [%1], 16;\n"
                 :: "r"(saddr), "l"(gaddr) : "memory");
}
__device__ __forceinline__ uint32_t pack_bf16x2(float a, float b) {
    __nv_bfloat162 p = __floats2bfloat162_rn(a, b);
    return *(uint32_t*)&p;
}

// ---------------------------------------------------------------------------
// fp32 -> bf16 (lossless).  8 elems/thread/iter.
// ---------------------------------------------------------------------------
__global__ __launch_bounds__(256) void cvt_kernel(
    const float* __restrict__ src, __nv_bfloat16* __restrict__ dst, size_t n8)
{
    const size_t stride = (size_t)gridDim.x * 256;
    for (size_t i = (size_t)blockIdx.x * 256 + threadIdx.x; i < n8; i += stride) {
        const float4* p = (const float4*)(src + i * 8);
        float4 v0 = p[0], v1 = p[1];
        uint4 o = make_uint4(pack_bf16x2(v0.x, v0.y), pack_bf16x2(v0.z, v0.w),
                             pack_bf16x2(v1.x, v1.y), pack_bf16x2(v1.z, v1.w));
        *(uint4*)(dst + i * 8) = o;
    }
}

// ---------------------------------------------------------------------------
// GEMM: C[n,v] = sum_h A[n,h]*B[v,h]  (bf16 in, fp32 accum, bf16 out)
// CTA 128x128x64, 8 warps (2x4), warp 64x32, k16 mma + ldmatrix (frozen core).
// THREE-stage cp.async pipeline (96KB smem, still 2 CTAs/SM): always-commit,
// wait_group 2 -> stage kt guaranteed complete, prefetch distance 2 ktiles.
// Fused fp32->bf16 side-job (W_t) + epilogue per-row sumexp partials.
// ---------------------------------------------------------------------------
__global__ __launch_bounds__(256, 2) void gemm_bf16_kernel(
    const __nv_bfloat16* __restrict__ A,
    const __nv_bfloat16* __restrict__ B,
    __nv_bfloat16* __restrict__ C,
    float* __restrict__ PSE,
    int H,
    const float* __restrict__ cvt_src,   // may be null
    __nv_bfloat16* __restrict__ cvt_dst,
    size_t cvt_n4)
{
    extern __shared__ char smem[];
    const uint32_t sbase = (uint32_t)__cvta_generic_to_shared(smem);

    const int tid   = threadIdx.x;
    const int lane  = tid & 31;
    const int warp  = tid >> 5;
    const int warp_m = warp >> 2;
    const int warp_n = warp & 3;
    const int m0 = blockIdx.x * 128;
    const int v0 = blockIdx.y * 128;

    float acc[4][4][4];
    #pragma unroll
    for (int i = 0; i < 4; i++)
        #pragma unroll
        for (int j = 0; j < 4; j++)
            #pragma unroll
            for (int k = 0; k < 4; k++) acc[i][j][k] = 0.f;

    const int ktiles = H >> 6;
    const int lr = tid >> 3;
    const int lc = tid & 7;
    const size_t flat_cta = (size_t)blockIdx.y * gridDim.x + blockIdx.x;

    size_t aoff[4], boff[4];
    #pragma unroll
    for (int j = 0; j < 4; j++) {
        aoff[j] = (size_t)(m0 + lr + j * 32) * H;
        int vr = v0 + lr + j * 32;
        if (vr > VDIM - 1) vr = VDIM - 1;
        boff[j] = (size_t)vr * H;
    }

    auto load_stage = [&](int slot, int kt) {
        const int k0 = kt * 64;
        const uint32_t aB = sbase + slot * 32768;
        const uint32_t bB = aB + 16384;
        #pragma unroll
        for (int j = 0; j < 4; j++) {
            cp16(aB + swz(lr + j * 32, lc), A + aoff[j] + k0 + lc * 8);
            cp16(bB + swz(lr + j * 32, lc), B + boff[j] + k0 + lc * 8);
        }
    };

    // Prologue: stages 0 and 1 committed as separate groups
    load_stage(0, 0);
    asm volatile("cp.async.commit_group;\n" ::: "memory");
    if (ktiles > 1) load_stage(1, 1);
    asm volatile("cp.async.commit_group;\n" ::: "memory");

    for (int kt = 0; kt < ktiles; kt++) {
        // Fused-cvt side job: LDG early, STG at iteration end.
        float4 cv;
        bool cvalid = false;
        size_t cq = 0;
        if (cvt_src) {
            cq = (flat_cta * (size_t)ktiles + kt) * 256 + tid;
            if (cq < cvt_n4) { cv = *(const float4*)(cvt_src + cq * 4); cvalid = true; }
        }

        // Prefetch stage kt+2 (slot of kt-1, closed by last iteration's barrier)
        if (kt + 2 < ktiles) load_stage((kt + 2) % 3, kt + 2);
        asm volatile("cp.async.commit_group;\n" ::: "memory");   // always
        asm volatile("cp.async.wait_group 2;\n" ::: "memory");   // stage kt done
        __syncthreads();

        const uint32_t aBase = sbase + (kt % 3) * 32768;
        const uint32_t bBase = aBase + 16384;

        #pragma unroll
        for (int kk = 0; kk < 4; kk++) {
            uint32_t a[4][4], b[4][2];
            #pragma unroll
            for (int mf = 0; mf < 4; mf++) {
                uint32_t row = warp_m * 64 + mf * 16 + (lane & 15);
                uint32_t chunk = kk * 2 + (lane >> 4);
                asm volatile("ldmatrix.sync.aligned.m8n8.x4.shared.b16 {%0,%1,%2,%3}, [%4];\n"
                    : "=r"(a[mf][0]), "=r"(a[mf][1]), "=r"(a[mf][2]), "=r"(a[mf][3])
                    : "r"(aBase + swz(row, chunk)));
            }
            #pragma unroll
            for (int nf = 0; nf < 4; nf++) {
                uint32_t row = warp_n * 32 + nf * 8 + (lane & 7);
                uint32_t chunk = kk * 2 + ((lane >> 3) & 1);
                asm volatile("ldmatrix.sync.aligned.m8n8.x2.shared.b16 {%0,%1}, [%2];\n"
                    : "=r"(b[nf][0]), "=r"(b[nf][1]) : "r"(bBase + swz(row, chunk)));
            }
            #pragma unroll
            for (int mf = 0; mf < 4; mf++)
                #pragma unroll
                for (int nf = 0; nf < 4; nf++)
                    asm volatile(
                        "mma.sync.aligned.m16n8k16.row.col.f32.bf16.bf16.f32 "
                        "{%0,%1,%2,%3}, {%4,%5,%6,%7}, {%8,%9}, {%0,%1,%2,%3};\n"
                        : "+f"(acc[mf][nf][0]), "+f"(acc[mf][nf][1]),
                          "+f"(acc[mf][nf][2]), "+f"(acc[mf][nf][3])
                        : "r"(a[mf][0]), "r"(a[mf][1]), "r"(a[mf][2]), "r"(a[mf][3]),
                          "r"(b[nf][0]), "r"(b[nf][1]));
        }

        if (cvalid) {
            *(uint2*)(cvt_dst + cq * 4) =
                make_uint2(pack_bf16x2(cv.x, cv.y), pack_bf16x2(cv.z, cv.w));
        }
        __syncthreads();   // closes compute of stage kt (slot reused at kt+3)
    }

    // ---- Epilogue: bf16 stores + per-row sumexp partials ----
    float* part = (float*)smem;   // mainloop done; reuse smem
    const int row_in = lane >> 2;
    const int col_in = (lane & 3) * 2;
    const int pidx = warp_n * 4 + (lane & 3);

    #pragma unroll
    for (int mf = 0; mf < 4; mf++) {
        float rs0 = 0.f, rs1 = 0.f;
        int rloc = warp_m * 64 + mf * 16 + row_in;
        int n0 = m0 + rloc;
        #pragma unroll
        for (int nf = 0; nf < 4; nf++) {
            int v = v0 + warp_n * 32 + nf * 8 + col_in;
            __nv_bfloat162 p0 = __floats2bfloat162_rn(acc[mf][nf][0], acc[mf][nf][1]);
            __nv_bfloat162 p1 = __floats2bfloat162_rn(acc[mf][nf][2], acc[mf][nf][3]);
            __nv_bfloat16* r0 = C + (size_t)n0 * VPAD;
            __nv_bfloat16* r1 = C + (size_t)(n0 + 8) * VPAD;
            if (v + 1 < VDIM) {
                *(__nv_bfloat162*)(r0 + v) = p0;
                *(__nv_bfloat162*)(r1 + v) = p1;
            } else if (v < VDIM) {
                r0[v] = p0.x;
                r1[v] = p1.x;
            }
            if (v < VDIM) {
                rs0 += __expf(__bfloat162float(p0.x));
                rs1 += __expf(__bfloat162float(p1.x));
            }
            if (v + 1 < VDIM) {
                rs0 += __expf(__bfloat162float(p0.y));
                rs1 += __expf(__bfloat162float(p1.y));
            }
        }
        part[rloc * 17 + pidx]       = rs0;
        part[(rloc + 8) * 17 + pidx] = rs1;
    }
    __syncthreads();
    if (tid < 128) {
        float s = 0.f;
        #pragma unroll
        for (int i = 0; i < 16; i++) s += part[tid * 17 + i];
        PSE[(size_t)(m0 + tid) * NVT + blockIdx.y] = s;
    }
}

// ---------------------------------------------------------------------------
// Deterministic lse from tile partials: one thread per row.
// ---------------------------------------------------------------------------
__global__ __launch_bounds__(256) void lse_reduce_kernel(
    const float* __restrict__ pse, float* __restrict__ lse_out)
{
    int n = blockIdx.x * 256 + threadIdx.x;
    if (n < NROWS) {
        const float* p = pse + (size_t)n * NVT;
        float s = 0.f;
        for (int j = 0; j < NVT; j++) s += p[j];
        lse_out[n] = __logf(s);
    }
}

// ---------------------------------------------------------------------------
// Per-row JSD terms + CE.  uint4 loads: 8 logits per LDG.128.
// ---------------------------------------------------------------------------
#define NOCT (VDIM / 8)   // 6282 full octets; tail element VDIM-1 by thread 0
__global__ __launch_bounds__(256) void rowloss_kernel(const int* __restrict__ target) {
    const int n = blockIdx.x;
    const __nv_bfloat16* rs = g_logits_s + (size_t)n * VPAD;
    const __nv_bfloat16* rt = g_logits_t + (size_t)n * VPAD;
    const uint4* rs4 = (const uint4*)rs;
    const uint4* rt4 = (const uint4*)rt;
    const float ls = g_lse[n];
    const float lt = g_lse[NROWS + n];

    float as = 0.f, at = 0.f;
    for (int p = threadIdx.x; p < NOCT; p += 256) {
        uint4 sv4 = rs4[p], tv4 = rt4[p];
        const uint32_t* sw = (const uint32_t*)&sv4;
        const uint32_t* tw = (const uint32_t*)&tv4;
        #pragma unroll
        for (int w = 0; w < 4; w++) {
            __nv_bfloat162 s2v = *(const __nv_bfloat162*)&sw[w];
            __nv_bfloat162 t2v = *(const __nv_bfloat162*)&tw[w];
            #pragma unroll
            for (int h = 0; h < 2; h++) {
                float sv = __bfloat162float(h ? s2v.y : s2v.x);
                float tv = __bfloat162float(h ? t2v.y : t2v.x);
                float slp = sv - ls, tlp = tv - lt;
                float sp = __expf(slp), tp = __expf(tlp);
                float lm = __logf(0.5f * sp + 0.5f * tp);   // BETA = 0.5
                as += sp * (slp - lm);
                at += tp * (tlp - lm);
            }
        }
    }
    if (threadIdx.x == 0) {
        float slp = __bfloat162float(rs[VDIM - 1]) - ls;
        float tlp = __bfloat162float(rt[VDIM - 1]) - lt;
        float sp = __expf(slp), tp = __expf(tlp);
        float lm = __logf(0.5f * sp + 0.5f * tp);
        as += sp * (slp - lm);
        at += tp * (tlp - lm);
    }
    __shared__ float sh0[256], sh1[256];
    sh0[threadIdx.x] = as; sh1[threadIdx.x] = at;
    __syncthreads();
    for (int off = 128; off > 0; off >>= 1) {
        if (threadIdx.x < off) {
            sh0[threadIdx.x] += sh0[threadIdx.x + off];
            sh1[threadIdx.x] += sh1[threadIdx.x + off];
        }
        __syncthreads();
    }
    if (threadIdx.x == 0) {
        g_row_kls[n] = sh0[0];
        g_row_klt[n] = sh1[0];
        int tg = target[n];
        bool valid = (tg != -100);
        int tgs = valid ? tg : 0;
        g_row_ce[n]    = valid ? (ls - __bfloat162float(rs[tgs])) : 0.f;
        g_row_valid[n] = valid ? 1.f : 0.f;
    }
}

// ---------------------------------------------------------------------------
// Final combine -> scalar loss (deterministic).
// ---------------------------------------------------------------------------
__global__ __launch_bounds__(256) void combine_kernel(float* __restrict__ out) {
    __shared__ float s0[256], s1[256], s2[256], s3[256];
    float a = 0.f, b = 0.f, c = 0.f, d = 0.f;
    for (int n = threadIdx.x; n < NROWS; n += 256) {
        a += g_row_ce[n];
        b += g_row_valid[n];
        c += g_row_kls[n];
        d += g_row_klt[n];
    }
    s0[threadIdx.x] = a; s1[threadIdx.x] = b; s2[threadIdx.x] = c; s3[threadIdx.x] = d;
    __syncthreads();
    for (int off = 128; off > 0; off >>= 1) {
        if (threadIdx.x < off) {
            s0[threadIdx.x] += s0[threadIdx.x + off];
            s1[threadIdx.x] += s1[threadIdx.x + off];
            s2[threadIdx.x] += s2[threadIdx.x + off];
            s3[threadIdx.x] += s3[threadIdx.x + off];
        }
        __syncthreads();
    }
    if (threadIdx.x == 0) {
        float hard = s0[0] / s1[0];
        float jsd  = (0.5f * s3[0] + 0.5f * s2[0]) / (float)NROWS;  // BETA=0.5
        out[0] = 0.5f * hard + 0.5f * jsd;
    }
}

// ---------------------------------------------------------------------------
// Launch.  Single stream; W_t cvt fused into the student GEMM.
// ---------------------------------------------------------------------------
extern "C" void kernel_launch(void* const* d_in, const int* in_sizes, int n_in,
                              void* d_out, int out_size) {
    const float* student = nullptr;
    const float* W_s     = nullptr;
    const float* teacher = nullptr;
    const float* W_t     = nullptr;
    const int*   target  = nullptr;

    for (int i = 0; i < n_in; i++) {
        long sz = in_sizes[i];
        if      (sz == (long)NROWS * H_S)      student = (const float*)d_in[i];
        else if (sz == (long)VDIM  * H_S)      W_s     = (const float*)d_in[i];
        else if (sz == (long)NROWS * H_T)      teacher = (const float*)d_in[i];
        else if (sz == (long)VDIM  * H_T)      W_t     = (const float*)d_in[i];
        else if (sz == (long)NROWS)            target  = (const int*)d_in[i];
    }

    __nv_bfloat16 *Cs, *Ct, *Wsb, *Wtb, *asb, *atb;
    float *lse, *pse_s, *pse_t;
    cudaGetSymbolAddress((void**)&Cs,    g_logits_s);
    cudaGetSymbolAddress((void**)&Ct,    g_logits_t);
    cudaGetSymbolAddress((void**)&Wsb,   g_Ws_bf);
    cudaGetSymbolAddress((void**)&Wtb,   g_Wt_bf);
    cudaGetSymbolAddress((void**)&asb,   g_as_bf);
    cudaGetSymbolAddress((void**)&atb,   g_at_bf);
    cudaGetSymbolAddress((void**)&lse,   g_lse);
    cudaGetSymbolAddress((void**)&pse_s, g_pse_s);
    cudaGetSymbolAddress((void**)&pse_t, g_pse_t);

    cudaFuncSetAttribute(gemm_bf16_kernel,
                         cudaFuncAttributeMaxDynamicSharedMemorySize, 98304);

    // Serial conversions needed before the student GEMM
    cvt_kernel<<<1024, 256>>>(student, asb, (size_t)NROWS * H_S / 8);
    cvt_kernel<<<1024, 256>>>(teacher, atb, (size_t)NROWS * H_T / 8);
    cvt_kernel<<<8192, 256>>>(W_s,     Wsb, (size_t)VDIM  * H_S / 8);

    dim3 ggrid(NROWS / 128, NVT);   // (16, 393), M innermost for L2 reuse

    // Student GEMM + fused W_t conversion (in-kernel overlap)
    gemm_bf16_kernel<<<ggrid, 256, 98304>>>(
        asb, Wsb, Cs, pse_s, H_S,
        W_t, Wtb, (size_t)VDIM * H_T / 4);

    // Teacher GEMM (W_t now converted; same-stream ordering)
    gemm_bf16_kernel<<<ggrid, 256, 98304>>>(
        atb, Wtb, Ct, pse_t, H_T,
        nullptr, nullptr, 0);

    lse_reduce_kernel<<<8, 256>>>(pse_s, lse);
    lse_reduce_kernel<<<8, 256>>>(pse_t, lse + NROWS);
    rowloss_kernel<<<NROWS, 256>>>(target);
    combine_kernel<<<1, 256>>>((float*)d_out);
}

// round 15
// speedup vs baseline: 1.1067x; 1.1067x over previous
#include <cuda_runtime.h>
#include <cuda_bf16.h>
#include <cstdint>
#include <math.h>

// Problem constants
#define NROWS 2048
#define VDIM  50257
#define VPAD  50272   // bf16 row stride
#define H_S   2048
#define H_T   4096
#define NVT   393     // number of 128-wide v tiles

// Scratch (static device allocations)
__device__ __nv_bfloat16 g_logits_s[(size_t)NROWS * VPAD];  // 206 MB
__device__ __nv_bfloat16 g_logits_t[(size_t)NROWS * VPAD];  // 206 MB
__device__ __nv_bfloat16 g_Ws_bf[(size_t)VDIM * H_S];       // 206 MB
__device__ __nv_bfloat16 g_Wt_bf[(size_t)VDIM * H_T];       // 412 MB
__device__ __nv_bfloat16 g_as_bf[(size_t)NROWS * H_S];
__device__ __nv_bfloat16 g_at_bf[(size_t)NROWS * H_T];
__device__ float g_pse_s[(size_t)NROWS * NVT];  // per-tile sumexp partials
__device__ float g_pse_t[(size_t)NROWS * NVT];
__device__ float g_lse[2 * NROWS];
__device__ float g_row_ce[NROWS];
__device__ float g_row_valid[NROWS];
__device__ float g_row_kls[NROWS];
__device__ float g_row_klt[NROWS];

// ---------------------------------------------------------------------------
// Helpers
// ---------------------------------------------------------------------------
__device__ __forceinline__ uint32_t swz(uint32_t row, uint32_t chunk) {
    return row * 128u + ((chunk ^ (row & 7u)) << 4);
}
__device__ __forceinline__ void cp16(uint32_t saddr, const void* gaddr) {
    asm volatile("cp.async.cg.shared.global [%0], [%1], 16;\n"
                 :: "r"(saddr), "l"(gaddr) : "memory");
}
__device__ __forceinline__ uint32_t pack_bf16x2(float a, float b) {
    __nv_bfloat162 p = __floats2bfloat162_rn(a, b);
    return *(uint32_t*)&p;
}

// ---------------------------------------------------------------------------
// fp32 -> bf16 (lossless).  8 elems/thread/iter.
// ---------------------------------------------------------------------------
__global__ __launch_bounds__(256) void cvt_kernel(
    const float* __restrict__ src, __nv_bfloat16* __restrict__ dst, size_t n8)
{
    const size_t stride = (size_t)gridDim.x * 256;
    for (size_t i = (size_t)blockIdx.x * 256 + threadIdx.x; i < n8; i += stride) {
        const float4* p = (const float4*)(src + i * 8);
        float4 v0 = p[0], v1 = p[1];
        uint4 o = make_uint4(pack_bf16x2(v0.x, v0.y), pack_bf16x2(v0.z, v0.w),
                             pack_bf16x2(v1.x, v1.y), pack_bf16x2(v1.z, v1.w));
        *(uint4*)(dst + i * 8) = o;
    }
}

// ---------------------------------------------------------------------------
// GEMM: C[n,v] = sum_h A[n,h]*B[v,h]  (bf16 in, fp32 accum, bf16 out)
// CTA 128x128x64, 8 warps (2x4), warp 64x32, k16 mma + ldmatrix (frozen core).
// Two-stage cp.async, ONE barrier per k-tile:
//   wait_group 0 -> sync -> issue next stage -> compute.
// The top barrier proves all warps finished compute(kt-1), so overwriting
// slot (kt+1)%2 (last read at kt-1) is safe.
// Fused fp32->bf16 side-job (W_t) + epilogue per-row sumexp partials.
// ---------------------------------------------------------------------------
__global__ __launch_bounds__(256, 2) void gemm_bf16_kernel(
    const __nv_bfloat16* __restrict__ A,
    const __nv_bfloat16* __restrict__ B,
    __nv_bfloat16* __restrict__ C,
    float* __restrict__ PSE,
    int H,
    const float* __restrict__ cvt_src,   // may be null
    __nv_bfloat16* __restrict__ cvt_dst,
    size_t cvt_n4)
{
    extern __shared__ char smem[];
    const uint32_t sbase = (uint32_t)__cvta_generic_to_shared(smem);

    const int tid   = threadIdx.x;
    const int lane  = tid & 31;
    const int warp  = tid >> 5;
    const int warp_m = warp >> 2;
    const int warp_n = warp & 3;
    const int m0 = blockIdx.x * 128;
    const int v0 = blockIdx.y * 128;

    float acc[4][4][4];
    #pragma unroll
    for (int i = 0; i < 4; i++)
        #pragma unroll
        for (int j = 0; j < 4; j++)
            #pragma unroll
            for (int k = 0; k < 4; k++) acc[i][j][k] = 0.f;

    const int ktiles = H >> 6;
    const int lr = tid >> 3;
    const int lc = tid & 7;
    const size_t flat_cta = (size_t)blockIdx.y * gridDim.x + blockIdx.x;

    size_t aoff[4], boff[4];
    #pragma unroll
    for (int j = 0; j < 4; j++) {
        aoff[j] = (size_t)(m0 + lr + j * 32) * H;
        int vr = v0 + lr + j * 32;
        if (vr > VDIM - 1) vr = VDIM - 1;
        boff[j] = (size_t)vr * H;
    }

    auto load_stage = [&](int slot, int kt) {
        const int k0 = kt * 64;
        const uint32_t aB = sbase + slot * 32768;
        const uint32_t bB = aB + 16384;
        #pragma unroll
        for (int j = 0; j < 4; j++) {
            cp16(aB + swz(lr + j * 32, lc), A + aoff[j] + k0 + lc * 8);
            cp16(bB + swz(lr + j * 32, lc), B + boff[j] + k0 + lc * 8);
        }
        asm volatile("cp.async.commit_group;\n" ::: "memory");
    };

    // Prologue: stage 0
    load_stage(0, 0);

    for (int kt = 0; kt < ktiles; kt++) {
        // Fused-cvt side job: LDG early (independent of the pipeline).
        float4 cv;
        bool cvalid = false;
        size_t cq = 0;
        if (cvt_src) {
            cq = (flat_cta * (size_t)ktiles + kt) * 256 + tid;
            if (cq < cvt_n4) { cv = *(const float4*)(cvt_src + cq * 4); cvalid = true; }
        }

        asm volatile("cp.async.wait_group 0;\n" ::: "memory");  // stage kt landed
        __syncthreads();                                        // compute(kt-1) done
        if (kt + 1 < ktiles) load_stage((kt + 1) & 1, kt + 1);  // safe: slot idle

        const uint32_t aBase = sbase + (kt & 1) * 32768;
        const uint32_t bBase = aBase + 16384;

        #pragma unroll
        for (int kk = 0; kk < 4; kk++) {
            uint32_t a[4][4], b[4][2];
            #pragma unroll
            for (int mf = 0; mf < 4; mf++) {
                uint32_t row = warp_m * 64 + mf * 16 + (lane & 15);
                uint32_t chunk = kk * 2 + (lane >> 4);
                asm volatile("ldmatrix.sync.aligned.m8n8.x4.shared.b16 {%0,%1,%2,%3}, [%4];\n"
                    : "=r"(a[mf][0]), "=r"(a[mf][1]), "=r"(a[mf][2]), "=r"(a[mf][3])
                    : "r"(aBase + swz(row, chunk)));
            }
            #pragma unroll
            for (int nf = 0; nf < 4; nf++) {
                uint32_t row = warp_n * 32 + nf * 8 + (lane & 7);
                uint32_t chunk = kk * 2 + ((lane >> 3) & 1);
                asm volatile("ldmatrix.sync.aligned.m8n8.x2.shared.b16 {%0,%1}, [%2];\n"
                    : "=r"(b[nf][0]), "=r"(b[nf][1]) : "r"(bBase + swz(row, chunk)));
            }
            #pragma unroll
            for (int mf = 0; mf < 4; mf++)
                #pragma unroll
                for (int nf = 0; nf < 4; nf++)
                    asm volatile(
                        "mma.sync.aligned.m16n8k16.row.col.f32.bf16.bf16.f32 "
                        "{%0,%1,%2,%3}, {%4,%5,%6,%7}, {%8,%9}, {%0,%1,%2,%3};\n"
                        : "+f"(acc[mf][nf][0]), "+f"(acc[mf][nf][1]),
                          "+f"(acc[mf][nf][2]), "+f"(acc[mf][nf][3])
                        : "r"(a[mf][0]), "r"(a[mf][1]), "r"(a[mf][2]), "r"(a[mf][3]),
                          "r"(b[nf][0]), "r"(b[nf][1]));
        }

        if (cvalid) {
            *(uint2*)(cvt_dst + cq * 4) =
                make_uint2(pack_bf16x2(cv.x, cv.y), pack_bf16x2(cv.z, cv.w));
        }
        // no trailing barrier: next iteration's top barrier covers slot reuse
    }
    __syncthreads();   // all compute done before smem reuse in epilogue

    // ---- Epilogue: bf16 stores + per-row sumexp partials ----
    float* part = (float*)smem;   // mainloop done; reuse smem
    const int row_in = lane >> 2;
    const int col_in = (lane & 3) * 2;
    const int pidx = warp_n * 4 + (lane & 3);

    #pragma unroll
    for (int mf = 0; mf < 4; mf++) {
        float rs0 = 0.f, rs1 = 0.f;
        int rloc = warp_m * 64 + mf * 16 + row_in;
        int n0 = m0 + rloc;
        #pragma unroll
        for (int nf = 0; nf < 4; nf++) {
            int v = v0 + warp_n * 32 + nf * 8 + col_in;
            __nv_bfloat162 p0 = __floats2bfloat162_rn(acc[mf][nf][0], acc[mf][nf][1]);
            __nv_bfloat162 p1 = __floats2bfloat162_rn(acc[mf][nf][2], acc[mf][nf][3]);
            __nv_bfloat16* r0 = C + (size_t)n0 * VPAD;
            __nv_bfloat16* r1 = C + (size_t)(n0 + 8) * VPAD;
            if (v + 1 < VDIM) {
                *(__nv_bfloat162*)(r0 + v) = p0;
                *(__nv_bfloat162*)(r1 + v) = p1;
            } else if (v < VDIM) {
                r0[v] = p0.x;
                r1[v] = p1.x;
            }
            if (v < VDIM) {
                rs0 += __expf(__bfloat162float(p0.x));
                rs1 += __expf(__bfloat162float(p1.x));
            }
            if (v + 1 < VDIM) {
                rs0 += __expf(__bfloat162float(p0.y));
                rs1 += __expf(__bfloat162float(p1.y));
            }
        }
        part[rloc * 17 + pidx]       = rs0;
        part[(rloc + 8) * 17 + pidx] = rs1;
    }
    __syncthreads();
    if (tid < 128) {
        float s = 0.f;
        #pragma unroll
        for (int i = 0; i < 16; i++) s += part[tid * 17 + i];
        PSE[(size_t)(m0 + tid) * NVT + blockIdx.y] = s;
    }
}

// ---------------------------------------------------------------------------
// Deterministic lse from tile partials (both matrices in one launch).
// ---------------------------------------------------------------------------
__global__ __launch_bounds__(256) void lse_reduce_kernel(
    const float* __restrict__ pse_s, const float* __restrict__ pse_t,
    float* __restrict__ lse_out)
{
    int idx = blockIdx.x * 256 + threadIdx.x;
    if (idx < 2 * NROWS) {
        const float* p = (idx < NROWS ? pse_s + (size_t)idx * NVT
                                      : pse_t + (size_t)(idx - NROWS) * NVT);
        float s = 0.f;
        for (int j = 0; j < NVT; j++) s += p[j];
        lse_out[idx] = __logf(s);
    }
}

// ---------------------------------------------------------------------------
// Per-row JSD terms + CE.  uint4 loads: 8 logits per LDG.128.
// ---------------------------------------------------------------------------
#define NOCT (VDIM / 8)   // 6282 full octets; tail element VDIM-1 by thread 0
__global__ __launch_bounds__(256) void rowloss_kernel(const int* __restrict__ target) {
    const int n = blockIdx.x;
    const __nv_bfloat16* rs = g_logits_s + (size_t)n * VPAD;
    const __nv_bfloat16* rt = g_logits_t + (size_t)n * VPAD;
    const uint4* rs4 = (const uint4*)rs;
    const uint4* rt4 = (const uint4*)rt;
    const float ls = g_lse[n];
    const float lt = g_lse[NROWS + n];

    float as = 0.f, at = 0.f;
    for (int p = threadIdx.x; p < NOCT; p += 256) {
        uint4 sv4 = rs4[p], tv4 = rt4[p];
        const uint32_t* sw = (const uint32_t*)&sv4;
        const uint32_t* tw = (const uint32_t*)&tv4;
        #pragma unroll
        for (int w = 0; w < 4; w++) {
            __nv_bfloat162 s2v = *(const __nv_bfloat162*)&sw[w];
            __nv_bfloat162 t2v = *(const __nv_bfloat162*)&tw[w];
            #pragma unroll
            for (int h = 0; h < 2; h++) {
                float sv = __bfloat162float(h ? s2v.y : s2v.x);
                float tv = __bfloat162float(h ? t2v.y : t2v.x);
                float slp = sv - ls, tlp = tv - lt;
                float sp = __expf(slp), tp = __expf(tlp);
                float lm = __logf(0.5f * sp + 0.5f * tp);   // BETA = 0.5
                as += sp * (slp - lm);
                at += tp * (tlp - lm);
            }
        }
    }
    if (threadIdx.x == 0) {
        float slp = __bfloat162float(rs[VDIM - 1]) - ls;
        float tlp = __bfloat162float(rt[VDIM - 1]) - lt;
        float sp = __expf(slp), tp = __expf(tlp);
        float lm = __logf(0.5f * sp + 0.5f * tp);
        as += sp * (slp - lm);
        at += tp * (tlp - lm);
    }
    __shared__ float sh0[256], sh1[256];
    sh0[threadIdx.x] = as; sh1[threadIdx.x] = at;
    __syncthreads();
    for (int off = 128; off > 0; off >>= 1) {
        if (threadIdx.x < off) {
            sh0[threadIdx.x] += sh0[threadIdx.x + off];
            sh1[threadIdx.x] += sh1[threadIdx.x + off];
        }
        __syncthreads();
    }
    if (threadIdx.x == 0) {
        g_row_kls[n] = sh0[0];
        g_row_klt[n] = sh1[0];
        int tg = target[n];
        bool valid = (tg != -100);
        int tgs = valid ? tg : 0;
        g_row_ce[n]    = valid ? (ls - __bfloat162float(rs[tgs])) : 0.f;
        g_row_valid[n] = valid ? 1.f : 0.f;
    }
}

// ---------------------------------------------------------------------------
// Final combine -> scalar loss (deterministic).
// ---------------------------------------------------------------------------
__global__ __launch_bounds__(256) void combine_kernel(float* __restrict__ out) {
    __shared__ float s0[256], s1[256], s2[256], s3[256];
    float a = 0.f, b = 0.f, c = 0.f, d = 0.f;
    for (int n = threadIdx.x; n < NROWS; n += 256) {
        a += g_row_ce[n];
        b += g_row_valid[n];
        c += g_row_kls[n];
        d += g_row_klt[n];
    }
    s0[threadIdx.x] = a; s1[threadIdx.x] = b; s2[threadIdx.x] = c; s3[threadIdx.x] = d;
    __syncthreads();
    for (int off = 128; off > 0; off >>= 1) {
        if (threadIdx.x < off) {
            s0[threadIdx.x] += s0[threadIdx.x + off];
            s1[threadIdx.x] += s1[threadIdx.x + off];
            s2[threadIdx.x] += s2[threadIdx.x + off];
            s3[threadIdx.x] += s3[threadIdx.x + off];
        }
        __syncthreads();
    }
    if (threadIdx.x == 0) {
        float hard = s0[0] / s1[0];
        float jsd  = (0.5f * s3[0] + 0.5f * s2[0]) / (float)NROWS;  // BETA=0.5
        out[0] = 0.5f * hard + 0.5f * jsd;
    }
}

// ---------------------------------------------------------------------------
// Launch.  Single stream; W_t cvt fused into the student GEMM.
// ---------------------------------------------------------------------------
extern "C" void kernel_launch(void* const* d_in, const int* in_sizes, int n_in,
                              void* d_out, int out_size) {
    const float* student = nullptr;
    const float* W_s     = nullptr;
    const float* teacher = nullptr;
    const float* W_t     = nullptr;
    const int*   target  = nullptr;

    for (int i = 0; i < n_in; i++) {
        long sz = in_sizes[i];
        if      (sz == (long)NROWS * H_S)      student = (const float*)d_in[i];
        else if (sz == (long)VDIM  * H_S)      W_s     = (const float*)d_in[i];
        else if (sz == (long)NROWS * H_T)      teacher = (const float*)d_in[i];
        else if (sz == (long)VDIM  * H_T)      W_t     = (const float*)d_in[i];
        else if (sz == (long)NROWS)            target  = (const int*)d_in[i];
    }

    __nv_bfloat16 *Cs, *Ct, *Wsb, *Wtb, *asb, *atb;
    float *lse, *pse_s, *pse_t;
    cudaGetSymbolAddress((void**)&Cs,    g_logits_s);
    cudaGetSymbolAddress((void**)&Ct,    g_logits_t);
    cudaGetSymbolAddress((void**)&Wsb,   g_Ws_bf);
    cudaGetSymbolAddress((void**)&Wtb,   g_Wt_bf);
    cudaGetSymbolAddress((void**)&asb,   g_as_bf);
    cudaGetSymbolAddress((void**)&atb,   g_at_bf);
    cudaGetSymbolAddress((void**)&lse,   g_lse);
    cudaGetSymbolAddress((void**)&pse_s, g_pse_s);
    cudaGetSymbolAddress((void**)&pse_t, g_pse_t);

    cudaFuncSetAttribute(gemm_bf16_kernel,
                         cudaFuncAttributeMaxDynamicSharedMemorySize, 65536);

    // Serial conversions needed before the student GEMM
    cvt_kernel<<<1024, 256>>>(student, asb, (size_t)NROWS * H_S / 8);
    cvt_kernel<<<1024, 256>>>(teacher, atb, (size_t)NROWS * H_T / 8);
    cvt_kernel<<<8192, 256>>>(W_s,     Wsb, (size_t)VDIM  * H_S / 8);

    dim3 ggrid(NROWS / 128, NVT);   // (16, 393), M innermost for L2 reuse

    // Student GEMM + fused W_t conversion (in-kernel overlap)
    gemm_bf16_kernel<<<ggrid, 256, 65536>>>(
        asb, Wsb, Cs, pse_s, H_S,
        W_t, Wtb, (size_t)VDIM * H_T / 4);

    // Teacher GEMM (W_t now converted; same-stream ordering)
    gemm_bf16_kernel<<<ggrid, 256, 65536>>>(
        atb, Wtb, Ct, pse_t, H_T,
        nullptr, nullptr, 0);

    lse_reduce_kernel<<<16, 256>>>(pse_s, pse_t, lse);
    rowloss_kernel<<<NROWS, 256>>>(target);
    combine_kernel<<<1, 256>>>((float*)d_out);
}